// round 2
// baseline (speedup 1.0000x reference)
#include <cuda_runtime.h>

#define B_    8
#define N_    2048
#define FIN   256
#define FOUT  64
#define ALPHA 0.2f

#define NSPLIT    4
#define TILE_I    64
#define TILE_J    128
#define PS_STRIDE 132   // 64*132: padded so phase-3 row reads hit distinct banks

// Scratch (device globals: allocation-free rule)
__device__ float g_Wh[B_ * N_ * FOUT];                 // 4 MB
__device__ float g_esrc[B_ * N_];
__device__ float g_edst[B_ * N_];
__device__ float g_part[NSPLIT][B_ * N_ * FOUT];       // 16 MB unnormalized partials
__device__ float g_rs[NSPLIT][B_ * N_];                // partial row sums

// ---------------------------------------------------------------------------
// Kernel A: Wh = h @ W  (+ e_src, e_dst per node, fused)
// 1024 blocks x 256 threads; 16 rows/block; thread = (row, 4 consecutive outputs)
// ---------------------------------------------------------------------------
__global__ __launch_bounds__(256) void gat_wh(const float* __restrict__ h,
                                              const float* __restrict__ W,
                                              const float* __restrict__ a) {
    __shared__ float h_s[16 * FIN];
    int t = threadIdx.x;

    // cooperative load: 16 rows x 256 floats = 1024 float4
    const float4* hsrc = (const float4*)h;
#pragma unroll
    for (int q = 0; q < 4; q++)
        ((float4*)h_s)[t + q * 256] = hsrc[(size_t)blockIdx.x * 1024 + t + q * 256];
    __syncthreads();

    int r   = t >> 4;     // local row 0..15
    int og4 = t & 15;     // which float4 of the 64 outputs

    const float4* W4  = (const float4*)W;
    const float*  hrw = h_s + r * FIN;
    float4 acc = make_float4(0.f, 0.f, 0.f, 0.f);
#pragma unroll 8
    for (int k = 0; k < FIN; k++) {
        float  hv = hrw[k];
        float4 wv = W4[k * 16 + og4];
        acc.x += hv * wv.x; acc.y += hv * wv.y;
        acc.z += hv * wv.z; acc.w += hv * wv.w;
    }

    int row = blockIdx.x * 16 + r;
    ((float4*)g_Wh)[row * 16 + og4] = acc;

    float4 a1 = ((const float4*)a)[og4];
    float4 a2 = ((const float4*)(a + FOUT))[og4];
    float v1 = acc.x * a1.x + acc.y * a1.y + acc.z * a1.z + acc.w * a1.w;
    float v2 = acc.x * a2.x + acc.y * a2.y + acc.z * a2.z + acc.w * a2.w;
#pragma unroll
    for (int off = 8; off > 0; off >>= 1) {
        v1 += __shfl_xor_sync(0xffffffffu, v1, off);
        v2 += __shfl_xor_sync(0xffffffffu, v2, off);
    }
    if (og4 == 0) { g_esrc[row] = v1; g_edst[row] = v2; }
}

// ---------------------------------------------------------------------------
// Kernel B: fused mask + leaky_relu + exp + (p @ Wh) partial accumulation.
// Grid (32 i-tiles, 8 batch, 4 j-splits), 256 threads.
// Each block: 64 i-rows x 512 j (4 tiles of 128).
// Thread = (il = t>>2, part = t&3): accumulates acc[16] = outputs part*16..+15.
// No softmax max-subtraction needed (logits |e| <~ 12, exp safe in fp32),
// so partials across j-splits combine by plain addition in kernel C.
// ---------------------------------------------------------------------------
__global__ __launch_bounds__(256) void gat_main(const int* __restrict__ adj) {
    extern __shared__ float sm[];
    float* Wh_s = sm;                           // TILE_J * FOUT      = 8192
    float* p_s  = sm + TILE_J * FOUT;           // TILE_I * PS_STRIDE = 8448
    float* s_s  = p_s + TILE_I * PS_STRIDE;     // TILE_I

    int t  = threadIdx.x;
    int b  = blockIdx.y;
    int i0 = blockIdx.x * TILE_I;
    int js = blockIdx.z;
    int rowbase = b * N_;

    if (t < TILE_I) s_s[t] = g_esrc[rowbase + i0 + t];

    float acc[16];
#pragma unroll
    for (int q = 0; q < 16; q++) acc[q] = 0.f;
    float rs = 0.f;

    int il3  = t >> 2;
    int part = t & 3;
    __syncthreads();

#pragma unroll 1
    for (int jt = 0; jt < 4; jt++) {
        int j0 = js * (N_ / NSPLIT) + jt * TILE_J;

        // phase 1: Wh tile -> smem (128 x 64 fp32)
        const float4* wsrc = (const float4*)(g_Wh + (size_t)(rowbase + j0) * FOUT);
#pragma unroll
        for (int q = 0; q < 8; q++)
            ((float4*)Wh_s)[t + q * 256] = wsrc[t + q * 256];

        // phase 2: p tile = adj ? exp(leaky(s_i + d_j)) : 0
#pragma unroll
        for (int k = 0; k < 8; k++) {
            int idx4 = k * 256 + t;              // int4 index over 64x128 tile
            int il   = idx4 >> 5;                // 32 int4 per tile row
            int jq   = (idx4 & 31) << 2;
            int4   av = *(const int4*)(adj + (size_t)(rowbase + i0 + il) * N_ + j0 + jq);
            float4 dv = *(const float4*)(g_edst + rowbase + j0 + jq);
            float  s  = s_s[il];
            float4 pv; float x;
            x = s + dv.x; x = x > 0.f ? x : ALPHA * x; pv.x = av.x > 0 ? __expf(x) : 0.f;
            x = s + dv.y; x = x > 0.f ? x : ALPHA * x; pv.y = av.y > 0 ? __expf(x) : 0.f;
            x = s + dv.z; x = x > 0.f ? x : ALPHA * x; pv.z = av.z > 0 ? __expf(x) : 0.f;
            x = s + dv.w; x = x > 0.f ? x : ALPHA * x; pv.w = av.w > 0 ? __expf(x) : 0.f;
            *(float4*)(p_s + il * PS_STRIDE + jq) = pv;
        }
        __syncthreads();

        // phase 3: acc += p * Wh   (FMA-bound inner loop)
        const float4* whs4 = (const float4*)Wh_s;
        const float*  prow = p_s + il3 * PS_STRIDE;
#pragma unroll 4
        for (int jj = 0; jj < TILE_J; jj++) {
            float p = prow[jj];
            rs += p;
            float4 w0 = whs4[jj * 16 + part * 4 + 0];
            float4 w1 = whs4[jj * 16 + part * 4 + 1];
            float4 w2 = whs4[jj * 16 + part * 4 + 2];
            float4 w3 = whs4[jj * 16 + part * 4 + 3];
            acc[0]  += p * w0.x; acc[1]  += p * w0.y; acc[2]  += p * w0.z; acc[3]  += p * w0.w;
            acc[4]  += p * w1.x; acc[5]  += p * w1.y; acc[6]  += p * w1.z; acc[7]  += p * w1.w;
            acc[8]  += p * w2.x; acc[9]  += p * w2.y; acc[10] += p * w2.z; acc[11] += p * w2.w;
            acc[12] += p * w3.x; acc[13] += p * w3.y; acc[14] += p * w3.z; acc[15] += p * w3.w;
        }
        __syncthreads();
    }

    size_t obase = (size_t)(rowbase + i0 + il3) * FOUT + part * 16;
    float4* po = (float4*)(g_part[js] + obase);
    po[0] = make_float4(acc[0],  acc[1],  acc[2],  acc[3]);
    po[1] = make_float4(acc[4],  acc[5],  acc[6],  acc[7]);
    po[2] = make_float4(acc[8],  acc[9],  acc[10], acc[11]);
    po[3] = make_float4(acc[12], acc[13], acc[14], acc[15]);
    if (part == 0) g_rs[js][rowbase + i0 + il3] = rs;
}

// ---------------------------------------------------------------------------
// Kernel C: combine 4 j-split partials, normalize, ELU.
// ---------------------------------------------------------------------------
__device__ __forceinline__ float elu1(float x) { return x > 0.f ? x : expm1f(x); }

__global__ __launch_bounds__(256) void gat_norm(float* __restrict__ out) {
    int f4  = blockIdx.x * 256 + threadIdx.x;   // float4 index, 0..262143
    int row = f4 >> 4;
    float4 a0 = ((const float4*)g_part[0])[f4];
    float4 a1 = ((const float4*)g_part[1])[f4];
    float4 a2 = ((const float4*)g_part[2])[f4];
    float4 a3 = ((const float4*)g_part[3])[f4];
    float rs  = g_rs[0][row] + g_rs[1][row] + g_rs[2][row] + g_rs[3][row];
    float inv = 1.0f / rs;
    float4 v;
    v.x = elu1((a0.x + a1.x + a2.x + a3.x) * inv);
    v.y = elu1((a0.y + a1.y + a2.y + a3.y) * inv);
    v.z = elu1((a0.z + a1.z + a2.z + a3.z) * inv);
    v.w = elu1((a0.w + a1.w + a2.w + a3.w) * inv);
    ((float4*)out)[f4] = v;
}

// ---------------------------------------------------------------------------
extern "C" void kernel_launch(void* const* d_in, const int* in_sizes, int n_in,
                              void* d_out, int out_size) {
    const float* h   = (const float*)d_in[0];
    const int*   adj = (const int*)d_in[1];
    const float* W   = (const float*)d_in[2];
    const float* a   = (const float*)d_in[3];
    float*       out = (float*)d_out;

    const int smem_b = (TILE_J * FOUT + TILE_I * PS_STRIDE + TILE_I) * 4; // ~66.8 KB
    cudaFuncSetAttribute(gat_main, cudaFuncAttributeMaxDynamicSharedMemorySize, smem_b);

    gat_wh<<<(B_ * N_) / 16, 256>>>(h, W, a);

    dim3 gridB(N_ / TILE_I, B_, NSPLIT);   // (32, 8, 4) = 1024 blocks
    gat_main<<<gridB, 256, smem_b>>>(adj);

    gat_norm<<<(B_ * N_ * FOUT / 4) / 256, 256>>>(out);
}

// round 3
// speedup vs baseline: 2.8668x; 2.8668x over previous
#include <cuda_runtime.h>

#define B_     8
#define N_     2048
#define FIN    256
#define FOUT   64
#define ALPHA  0.2f

#define NSPLIT 8
#define TI     64
#define TJ     64
#define PST    68      // p_s row stride (floats): 8-row stride hits bank+16, 1-row stride bank+4

// Scratch (device globals: allocation-free rule)
__device__ float g_Whp[B_ * N_ * FOUT];            // pair-interleaved: [(b*N+j)>>1][o][j&1]
__device__ float g_esrc[B_ * N_];
__device__ float g_edst[B_ * N_];
__device__ float g_part[NSPLIT][B_ * N_ * FOUT];   // 32 MB unnormalized partials
__device__ float g_rs[NSPLIT][B_ * N_];

// packed fp32x2 FMA: d = a*b + d (elementwise on 2 lanes)
#define FMA2(d, a, b) asm("fma.rn.f32x2 %0, %1, %2, %0;" : "+l"(d) : "l"(a), "l"(b))

__device__ __forceinline__ float pair_sum(unsigned long long v) {
    float lo, hi;
    asm("mov.b64 {%0, %1}, %2;" : "=f"(lo), "=f"(hi) : "l"(v));
    return lo + hi;
}
__device__ __forceinline__ unsigned long long pack2(float lo, float hi) {
    unsigned long long r;
    asm("mov.b64 %0, {%1, %2};" : "=l"(r) : "f"(lo), "f"(hi));
    return r;
}

// ---------------------------------------------------------------------------
// Kernel A: Wh = h @ W (+ e_src/e_dst), W staged in smem pair-packed over k.
// 256 blocks x 256 threads, 64 h-rows per block.
// Thread = (rg = t>>4: 4 rows, op = t&15: outputs {2op,2op+1,2op+32,2op+33}).
// Accumulators packed over k-parity; FFMA2 throughout.
// ---------------------------------------------------------------------------
__global__ __launch_bounds__(256) void gat_wh(const float* __restrict__ h,
                                              const float* __restrict__ W,
                                              const float* __restrict__ a) {
    extern __shared__ float sA[];
    unsigned long long* Wp = (unsigned long long*)sA;   // 8192 ull = 64 KB: [kp][o] pair
    float* h_s = sA + 16384;                            // 64 rows x 36 stride = 9 KB

    int t = threadIdx.x;

    // stage W pairs: Wp[kp*64+o] = (W[2kp][o], W[2kp+1][o])
    for (int idx = t; idx < 8192; idx += 256) {
        int kp = idx >> 6, o = idx & 63;
        Wp[idx] = pack2(W[(2 * kp) * FOUT + o], W[(2 * kp + 1) * FOUT + o]);
    }

    int rg = t >> 4, op = t & 15;
    int row0 = blockIdx.x * 64;

    unsigned long long acc[4][4];
#pragma unroll
    for (int q = 0; q < 4; q++)
#pragma unroll
        for (int s = 0; s < 4; s++) acc[q][s] = 0ull;

    for (int kc = 0; kc < 8; kc++) {
        __syncthreads();
        // load h chunk: 64 rows x 32 k
#pragma unroll
        for (int q = 0; q < 2; q++) {
            int idx = q * 256 + t;
            int r = idx >> 3, f4 = idx & 7;
            *(float4*)(h_s + r * 36 + f4 * 4) =
                *(const float4*)(h + (size_t)(row0 + r) * FIN + kc * 32 + f4 * 4);
        }
        __syncthreads();
#pragma unroll
        for (int kpl = 0; kpl < 16; kpl++) {
            const ulonglong2* wrow = (const ulonglong2*)(Wp + (kc * 16 + kpl) * 64);
            ulonglong2 wa = wrow[op];        // outputs 2op, 2op+1
            ulonglong2 wb = wrow[op + 16];   // outputs 2op+32, 2op+33
#pragma unroll
            for (int q = 0; q < 4; q++) {
                unsigned long long hv =
                    *(const unsigned long long*)(h_s + (rg * 4 + q) * 36 + 2 * kpl);
                FMA2(acc[q][0], hv, wa.x);
                FMA2(acc[q][1], hv, wa.y);
                FMA2(acc[q][2], hv, wb.x);
                FMA2(acc[q][3], hv, wb.y);
            }
        }
    }

    int ov[4] = {2 * op, 2 * op + 1, 2 * op + 32, 2 * op + 33};
    float a1v[4], a2v[4];
#pragma unroll
    for (int s = 0; s < 4; s++) { a1v[s] = a[ov[s]]; a2v[s] = a[FOUT + ov[s]]; }

#pragma unroll
    for (int q = 0; q < 4; q++) {
        int grow = row0 + rg * 4 + q;
        float vals[4];
        float v1 = 0.f, v2 = 0.f;
#pragma unroll
        for (int s = 0; s < 4; s++) {
            vals[s] = pair_sum(acc[q][s]);
            v1 += vals[s] * a1v[s];
            v2 += vals[s] * a2v[s];
        }
        // pair-interleaved Wh store
        size_t base = (size_t)(grow >> 1) * 128 + (grow & 1);
#pragma unroll
        for (int s = 0; s < 4; s++) g_Whp[base + ov[s] * 2] = vals[s];
#pragma unroll
        for (int off = 1; off < 16; off <<= 1) {
            v1 += __shfl_xor_sync(0xffffffffu, v1, off);
            v2 += __shfl_xor_sync(0xffffffffu, v2, off);
        }
        if (op == 0) { g_esrc[grow] = v1; g_edst[grow] = v2; }
    }
}

// ---------------------------------------------------------------------------
// Kernel B: fused mask+leaky+exp+(p @ Wh). Grid (32 i-tiles, 8 b, 8 j-splits),
// 128 threads. Tile 64i x 64j, 4 tiles per block.
// Phase 3: thread = (ig = t>>4: rows ig+8m, op = t&15: outputs {2op,2op+1,2op+32,2op+33}).
// Accumulators packed over j-parity → p pair = contiguous LDS.64,
// Wh pair = contiguous (pair-interleaved layout). 32 FFMA2 per 10 LDS per jp.
// ---------------------------------------------------------------------------
__global__ __launch_bounds__(128) void gat_main(const int* __restrict__ adj) {
    extern __shared__ float sB[];
    float* Whp_s = sB;                  // 4096 floats (32 jp x 64 o pairs)
    float* p_s   = sB + 4096;           // 64 x PST
    float* s_s   = sB + 4096 + TI * PST;// 64

    int t  = threadIdx.x;
    int b  = blockIdx.y;
    int i0 = blockIdx.x * TI;
    int js = blockIdx.z;
    int rowbase = b * N_;

    if (t < 16)
        *(float4*)(s_s + t * 4) = *(const float4*)(g_esrc + rowbase + i0 + t * 4);

    int ig = t >> 4, op = t & 15;

    unsigned long long acc[8][4];
#pragma unroll
    for (int m = 0; m < 8; m++)
#pragma unroll
        for (int s = 0; s < 4; s++) acc[m][s] = 0ull;
    float rs_acc[8] = {0.f, 0.f, 0.f, 0.f, 0.f, 0.f, 0.f, 0.f};

#pragma unroll 1
    for (int jt = 0; jt < 4; jt++) {
        int j0 = js * 256 + jt * 64;
        __syncthreads();   // protect prior tile's smem reads (and s_s on iter 0)

        // phase 1: Whp tile (pair rows (rowbase+j0)/2 .. +31, 128 floats each)
        const float4* src = (const float4*)(g_Whp + ((size_t)(rowbase + j0) >> 1) * 128);
#pragma unroll
        for (int q = 0; q < 8; q++)
            ((float4*)Whp_s)[q * 128 + t] = src[q * 128 + t];

        // phase 2: p = adj ? exp(leaky(esrc_i + edst_j)) : 0 ; partial row sums
#pragma unroll
        for (int k = 0; k < 8; k++) {
            int idx = k * 128 + t;
            int il  = idx >> 4;
            int jq  = (idx & 15) << 2;
            int4   av = *(const int4*)(adj + (size_t)(rowbase + i0 + il) * N_ + j0 + jq);
            float4 dv = __ldg((const float4*)(g_edst + rowbase + j0 + jq));
            float  s  = s_s[il];
            float4 pv; float x;
            x = s + dv.x; x = x > 0.f ? x : ALPHA * x; pv.x = av.x > 0 ? __expf(x) : 0.f;
            x = s + dv.y; x = x > 0.f ? x : ALPHA * x; pv.y = av.y > 0 ? __expf(x) : 0.f;
            x = s + dv.z; x = x > 0.f ? x : ALPHA * x; pv.z = av.z > 0 ? __expf(x) : 0.f;
            x = s + dv.w; x = x > 0.f ? x : ALPHA * x; pv.w = av.w > 0 ? __expf(x) : 0.f;
            *(float4*)(p_s + il * PST + jq) = pv;
            float sum4 = (pv.x + pv.y) + (pv.z + pv.w);
#pragma unroll
            for (int off = 1; off < 16; off <<= 1)
                sum4 += __shfl_xor_sync(0xffffffffu, sum4, off);
            rs_acc[k] += sum4;   // valid on op==0 lanes (row il = k*8 + ig)
        }
        __syncthreads();

        // phase 3: acc += p-pair * Wh-pair
        const unsigned long long* wq = (const unsigned long long*)Whp_s;
#pragma unroll 4
        for (int jp = 0; jp < 32; jp++) {
            ulonglong2 wa = *(const ulonglong2*)(wq + jp * 64 + 2 * op);
            ulonglong2 wb = *(const ulonglong2*)(wq + jp * 64 + 2 * op + 32);
#pragma unroll
            for (int m = 0; m < 8; m++) {
                unsigned long long pp =
                    *(const unsigned long long*)(p_s + (ig + 8 * m) * PST + 2 * jp);
                FMA2(acc[m][0], pp, wa.x);
                FMA2(acc[m][1], pp, wa.y);
                FMA2(acc[m][2], pp, wb.x);
                FMA2(acc[m][3], pp, wb.y);
            }
        }
    }

    if (op == 0) {
#pragma unroll
        for (int k = 0; k < 8; k++)
            g_rs[js][rowbase + i0 + k * 8 + ig] = rs_acc[k];
    }

    float* po = g_part[js];
#pragma unroll
    for (int m = 0; m < 8; m++) {
        size_t grow = (size_t)(rowbase + i0 + ig + 8 * m);
        float2 v0 = make_float2(pair_sum(acc[m][0]), pair_sum(acc[m][1]));
        float2 v1 = make_float2(pair_sum(acc[m][2]), pair_sum(acc[m][3]));
        *(float2*)(po + grow * 64 + 2 * op)      = v0;
        *(float2*)(po + grow * 64 + 2 * op + 32) = v1;
    }
}

// ---------------------------------------------------------------------------
// Kernel C: combine 8 j-split partials, normalize, ELU.
// ---------------------------------------------------------------------------
__device__ __forceinline__ float elu1(float x) { return x > 0.f ? x : expm1f(x); }

__global__ __launch_bounds__(256) void gat_norm(float* __restrict__ out) {
    int f4  = blockIdx.x * 256 + threadIdx.x;   // 0..262143
    int row = f4 >> 4;
    float4 s = make_float4(0.f, 0.f, 0.f, 0.f);
    float rs = 0.f;
#pragma unroll
    for (int p = 0; p < NSPLIT; p++) {
        float4 v = ((const float4*)g_part[p])[f4];
        s.x += v.x; s.y += v.y; s.z += v.z; s.w += v.w;
        rs  += g_rs[p][row];
    }
    float inv = 1.0f / rs;
    float4 o;
    o.x = elu1(s.x * inv);
    o.y = elu1(s.y * inv);
    o.z = elu1(s.z * inv);
    o.w = elu1(s.w * inv);
    ((float4*)out)[f4] = o;
}

// ---------------------------------------------------------------------------
extern "C" void kernel_launch(void* const* d_in, const int* in_sizes, int n_in,
                              void* d_out, int out_size) {
    const float* h   = (const float*)d_in[0];
    const int*   adj = (const int*)d_in[1];
    const float* W   = (const float*)d_in[2];
    const float* a   = (const float*)d_in[3];
    float*       out = (float*)d_out;

    const int smemA = (16384 + 64 * 36) * 4;                 // 74.8 KB
    const int smemB = (4096 + TI * PST + TI) * 4;            // 34.1 KB
    cudaFuncSetAttribute(gat_wh,   cudaFuncAttributeMaxDynamicSharedMemorySize, smemA);
    cudaFuncSetAttribute(gat_main, cudaFuncAttributeMaxDynamicSharedMemorySize, smemB);

    gat_wh<<<(B_ * N_) / 64, 256, smemA>>>(h, W, a);

    dim3 gridB(N_ / TI, B_, NSPLIT);   // (32, 8, 8) = 2048 blocks
    gat_main<<<gridB, 128, smemB>>>(adj);

    gat_norm<<<(B_ * N_ * FOUT / 4) / 256, 256>>>(out);
}

// round 5
// speedup vs baseline: 5.0280x; 1.7539x over previous
#include <cuda_runtime.h>
#include <cstdint>

#define B_     8
#define N_     2048
#define FIN    256
#define FOUT   64
#define LOG2E  1.4426950408889634f

// Scratch (device globals: allocation-free rule)
__device__ float g_WhB[B_ * N_ * FOUT];   // [b][j>>3][o][j&7], tf32-pre-rounded
__device__ float g_esrc[B_ * N_];         // pre-scaled by log2(e)
__device__ float g_edst[B_ * N_];         // pre-scaled by log2(e)

// ---------------------------------------------------------------------------
// helpers
// ---------------------------------------------------------------------------
__device__ __forceinline__ uint32_t smem_u32(const void* p) {
    uint32_t a;
    asm("{ .reg .u64 t; cvta.to.shared.u64 t, %1; cvt.u32.u64 %0, t; }" : "=r"(a) : "l"(p));
    return a;
}
__device__ __forceinline__ void cpa16(uint32_t dst, const void* src) {
    asm volatile("cp.async.cg.shared.global [%0], [%1], 16;" :: "r"(dst), "l"(src));
}
#define CP_COMMIT() asm volatile("cp.async.commit_group;" ::: "memory")
#define CP_WAIT1()  asm volatile("cp.async.wait_group 1;" ::: "memory")

__device__ __forceinline__ float ex2f(float x) {
    float r; asm("ex2.approx.f32 %0, %1;" : "=f"(r) : "f"(x)); return r;
}
__device__ __forceinline__ uint32_t tf32u(float x) {
    uint32_t r; asm("cvt.rn.tf32.f32 %0, %1;" : "=r"(r) : "f"(x)); return r;
}
// D += A*B, m16n8k8 tf32 (base PTX ISA, compiles for compute_103)
#define MMA_TF32(d, a0, a1, a2, a3, b0, b1)                                   \
    asm volatile("mma.sync.aligned.m16n8k8.row.col.f32.tf32.tf32.f32 "        \
                 "{%0,%1,%2,%3}, {%4,%5,%6,%7}, {%8,%9}, {%0,%1,%2,%3};"      \
                 : "+f"((d)[0]), "+f"((d)[1]), "+f"((d)[2]), "+f"((d)[3])     \
                 : "r"(a0), "r"(a1), "r"(a2), "r"(a3), "r"(b0), "r"(b1))

// packed fp32x2 FMA (kernel A)
#define FMA2(d, a, b) asm("fma.rn.f32x2 %0, %1, %2, %0;" : "+l"(d) : "l"(a), "l"(b))
__device__ __forceinline__ float pair_sum(unsigned long long v) {
    float lo, hi;
    asm("mov.b64 {%0, %1}, %2;" : "=f"(lo), "=f"(hi) : "l"(v));
    return lo + hi;
}
__device__ __forceinline__ unsigned long long pack2(float lo, float hi) {
    unsigned long long r;
    asm("mov.b64 %0, {%1, %2};" : "=l"(r) : "f"(lo), "f"(hi));
    return r;
}

// ---------------------------------------------------------------------------
// Kernel A: Wh = h @ W (fp32 FFMA2). Stores g_WhB (tf32-rounded, fragment
// layout) and e_src/e_dst pre-scaled by log2(e). 256 blocks x 256 threads.
// ---------------------------------------------------------------------------
__global__ __launch_bounds__(256) void gat_wh(const float* __restrict__ h,
                                              const float* __restrict__ W,
                                              const float* __restrict__ a) {
    extern __shared__ float sA[];
    unsigned long long* Wp = (unsigned long long*)sA;   // 2048 ull = 16KB
    float* h_s = sA + 4096;                             // 64 rows x 36

    int t = threadIdx.x;
    int rg = t >> 4, op = t & 15;
    int row0 = blockIdx.x * 64;

    unsigned long long acc[4][4];
#pragma unroll
    for (int q = 0; q < 4; q++)
#pragma unroll
        for (int s = 0; s < 4; s++) acc[q][s] = 0ull;

    for (int wq = 0; wq < 4; wq++) {
        __syncthreads();
        for (int idx = t; idx < 2048; idx += 256) {
            int kpl = idx >> 6, o = idx & 63;
            int kp = wq * 32 + kpl;
            Wp[idx] = pack2(W[(2 * kp) * FOUT + o], W[(2 * kp + 1) * FOUT + o]);
        }
        for (int kcq = 0; kcq < 2; kcq++) {
            __syncthreads();
#pragma unroll
            for (int q = 0; q < 2; q++) {
                int idx = q * 256 + t;
                int r = idx >> 3, f4 = idx & 7;
                *(float4*)(h_s + r * 36 + f4 * 4) =
                    *(const float4*)(h + (size_t)(row0 + r) * FIN + wq * 64 + kcq * 32 + f4 * 4);
            }
            __syncthreads();
#pragma unroll
            for (int kpl = 0; kpl < 16; kpl++) {
                const ulonglong2* wrow = (const ulonglong2*)(Wp + (kcq * 16 + kpl) * 64);
                ulonglong2 wa = wrow[op];
                ulonglong2 wb = wrow[op + 16];
#pragma unroll
                for (int q = 0; q < 4; q++) {
                    unsigned long long hv =
                        *(const unsigned long long*)(h_s + (rg * 4 + q) * 36 + 2 * kpl);
                    FMA2(acc[q][0], hv, wa.x);
                    FMA2(acc[q][1], hv, wa.y);
                    FMA2(acc[q][2], hv, wb.x);
                    FMA2(acc[q][3], hv, wb.y);
                }
            }
        }
    }

    int ov[4] = {2 * op, 2 * op + 1, 2 * op + 32, 2 * op + 33};
    float a1v[4], a2v[4];
#pragma unroll
    for (int s = 0; s < 4; s++) { a1v[s] = a[ov[s]]; a2v[s] = a[FOUT + ov[s]]; }

#pragma unroll
    for (int q = 0; q < 4; q++) {
        int grow = row0 + rg * 4 + q;
        int b = grow >> 11, n = grow & (N_ - 1);
        float vals[4], v1 = 0.f, v2 = 0.f;
#pragma unroll
        for (int s = 0; s < 4; s++) {
            vals[s] = pair_sum(acc[q][s]);
            v1 += vals[s] * a1v[s];
            v2 += vals[s] * a2v[s];
        }
        // fragment-friendly layout: [b][n>>3][o][n&7]
        size_t base = ((size_t)b * 256 + (n >> 3)) * 512 + (n & 7);
#pragma unroll
        for (int s = 0; s < 4; s++)
            g_WhB[base + (size_t)ov[s] * 8] = __uint_as_float(tf32u(vals[s]));
#pragma unroll
        for (int off = 1; off < 16; off <<= 1) {
            v1 += __shfl_xor_sync(0xffffffffu, v1, off);
            v2 += __shfl_xor_sync(0xffffffffu, v2, off);
        }
        if (op == 0) {
            g_esrc[grow] = v1 * LOG2E;
            g_edst[grow] = v2 * LOG2E;
        }
    }
}

// ---------------------------------------------------------------------------
// Kernel B: fused mask+leaky+exp2 -> mma.sync tf32 P @ Wh, rowsum in regs.
// Grid (16,8)=128 blocks x 256 threads (8 warps).
// Warp w: rows (w&3)*32 .. +31 (two m16 fragments), j-half w>>2.
// k-permutation pi=[0,2,4,6,1,3,5,7]: lane (q=lane>>2, c=lane&3) handles
// adjacent j pair {2c,2c+1} -> int2 adj loads, LDS.64 B-fragment loads.
// Double-buffered cp.async staging of Wh chunks (64 j per half per chunk).
// ---------------------------------------------------------------------------
// smem: buf0 [0,33280), buf1 [33280,66560). Per buf: half0 B 16KB, half1 B
// 16KB at +16384, edst 512B at +32768. Epilogue reuses [0,34304).
#define SM_BUFSZ 33280
#define SM_TOTB  (2 * SM_BUFSZ)

__device__ __forceinline__ void prefetch_chunk(uint32_t smdst, const char* whsrc,
                                               const float* edsrc, int cc, int t) {
#pragma unroll
    for (int it = 0; it < 8; it++) {
        int idx = it * 256 + t;          // 16B units, 2048 total (32KB)
        int h2 = idx >> 10, u = idx & 1023;
        const char* src = whsrc + ((size_t)(h2 * 128 + cc * 8)) * 2048 + (size_t)u * 16;
        cpa16(smdst + h2 * 16384 + u * 16, src);
    }
    if (t < 32) {
        int h2 = t >> 4, u = t & 15;
        const char* src = (const char*)(edsrc + h2 * 1024 + cc * 64) + u * 16;
        cpa16(smdst + 32768 + h2 * 256 + u * 16, src);
    }
}

__global__ __launch_bounds__(256) void gat_attn(const int* __restrict__ adj,
                                                float* __restrict__ out) {
    extern __shared__ char sm[];
    uint32_t smb = smem_u32(sm);

    int t = threadIdx.x;
    int w = t >> 5, lane = t & 31;
    int q = lane >> 2, c = lane & 3;
    int b = blockIdx.y;
    int i0 = blockIdx.x * 128;
    int rowbase = b * N_;
    int h = w >> 2;            // j-half
    int wr = (w & 3) * 32;     // warp row base within tile

    const char*  whsrc = (const char*)(g_WhB + (size_t)b * N_ * FOUT);
    const float* edsrc = g_edst + rowbase;

    float es[4];
#pragma unroll
    for (int r = 0; r < 4; r++) es[r] = g_esrc[rowbase + i0 + wr + q + 8 * r];

    const int* adjb = adj + (size_t)(rowbase + i0 + wr + q) * N_ + h * 1024;

    prefetch_chunk(smb, whsrc, edsrc, 0, t); CP_COMMIT();
    prefetch_chunk(smb + SM_BUFSZ, whsrc, edsrc, 1, t); CP_COMMIT();

    float acc[2][8][4];
#pragma unroll
    for (int f = 0; f < 2; f++)
#pragma unroll
        for (int nt = 0; nt < 8; nt++)
#pragma unroll
            for (int s = 0; s < 4; s++) acc[f][nt][s] = 0.f;
    float rsum[4] = {0.f, 0.f, 0.f, 0.f};

#pragma unroll 1
    for (int cc = 0; cc < 16; cc++) {
        CP_WAIT1();
        __syncthreads();
        uint32_t bufb = smb + (cc & 1) * SM_BUFSZ;
        const float* Bc = (const float*)(sm + (cc & 1) * SM_BUFSZ + h * 16384);
        const float* Ec = (const float*)(sm + (cc & 1) * SM_BUFSZ + 32768 + h * 256);
        (void)bufb;

#pragma unroll 2
        for (int ks = 0; ks < 8; ks++) {
            float2 dv = *(const float2*)(Ec + ks * 8 + 2 * c);
            uint32_t pa[4][2];
#pragma unroll
            for (int r = 0; r < 4; r++) {
                int2 av = *(const int2*)(adjb + (size_t)(8 * r) * N_ + cc * 64 + ks * 8 + 2 * c);
                float x0 = es[r] + dv.x; x0 = fmaxf(x0, 0.2f * x0);
                float x1 = es[r] + dv.y; x1 = fmaxf(x1, 0.2f * x1);
                uint32_t u0 = tf32u(av.x > 0 ? ex2f(x0) : 0.f);
                uint32_t u1 = tf32u(av.y > 0 ? ex2f(x1) : 0.f);
                rsum[r] += __uint_as_float(u0) + __uint_as_float(u1);
                pa[r][0] = u0; pa[r][1] = u1;
            }
#pragma unroll
            for (int nt = 0; nt < 8; nt++) {
                float2 wv = *(const float2*)(Bc + ks * 512 + (nt * 8 + q) * 8 + 2 * c);
                uint32_t b0 = __float_as_uint(wv.x), b1 = __float_as_uint(wv.y);
                MMA_TF32(acc[0][nt], pa[0][0], pa[1][0], pa[0][1], pa[1][1], b0, b1);
                MMA_TF32(acc[1][nt], pa[2][0], pa[3][0], pa[2][1], pa[3][1], b0, b1);
            }
        }
        __syncthreads();
        if (cc + 2 < 16) prefetch_chunk(smb + (cc & 1) * SM_BUFSZ, whsrc, edsrc, cc + 2, t);
        CP_COMMIT();   // empty group at tail keeps wait_group accounting
    }

    // quad-reduce rowsums (butterfly: all lanes get full quad sum)
#pragma unroll
    for (int r = 0; r < 4; r++) {
        rsum[r] += __shfl_xor_sync(0xffffffffu, rsum[r], 1);
        rsum[r] += __shfl_xor_sync(0xffffffffu, rsum[r], 2);
    }

    // combine j-halves via smem, normalize, ELU, store (half 0 finishes)
    float* dsm = (float*)sm;                 // 128 x 66
    float* rsm = (float*)(sm + 33792);       // 128 floats
    __syncthreads();
    if (h == 1) {
#pragma unroll
        for (int f = 0; f < 2; f++) {
            int row0 = wr + 16 * f + q;
#pragma unroll
            for (int nt = 0; nt < 8; nt++) {
                *(float2*)(dsm + row0 * 66 + nt * 8 + 2 * c) =
                    make_float2(acc[f][nt][0], acc[f][nt][1]);
                *(float2*)(dsm + (row0 + 8) * 66 + nt * 8 + 2 * c) =
                    make_float2(acc[f][nt][2], acc[f][nt][3]);
            }
        }
        if (c == 0) {
#pragma unroll
            for (int r = 0; r < 4; r++) rsm[wr + q + 8 * r] = rsum[r];
        }
    }
    __syncthreads();
    if (h == 0) {
        float inv[4];
#pragma unroll
        for (int r = 0; r < 4; r++)
            inv[r] = 1.0f / (rsum[r] + rsm[wr + q + 8 * r]);
#pragma unroll
        for (int f = 0; f < 2; f++) {
            int row0 = wr + 16 * f + q;
            float i0v = inv[2 * f], i1v = inv[2 * f + 1];
            float* o0 = out + (size_t)(rowbase + i0 + row0) * FOUT;
            float* o1 = out + (size_t)(rowbase + i0 + row0 + 8) * FOUT;
#pragma unroll
            for (int nt = 0; nt < 8; nt++) {
                float2 d0 = *(const float2*)(dsm + row0 * 66 + nt * 8 + 2 * c);
                float2 d1 = *(const float2*)(dsm + (row0 + 8) * 66 + nt * 8 + 2 * c);
                float y;
                float2 v0, v1;
                y = (acc[f][nt][0] + d0.x) * i0v; v0.x = y > 0.f ? y : expm1f(y);
                y = (acc[f][nt][1] + d0.y) * i0v; v0.y = y > 0.f ? y : expm1f(y);
                y = (acc[f][nt][2] + d1.x) * i1v; v1.x = y > 0.f ? y : expm1f(y);
                y = (acc[f][nt][3] + d1.y) * i1v; v1.y = y > 0.f ? y : expm1f(y);
                *(float2*)(o0 + nt * 8 + 2 * c) = v0;
                *(float2*)(o1 + nt * 8 + 2 * c) = v1;
            }
        }
    }
}

// ---------------------------------------------------------------------------
extern "C" void kernel_launch(void* const* d_in, const int* in_sizes, int n_in,
                              void* d_out, int out_size) {
    const float* h   = (const float*)d_in[0];
    const int*   adj = (const int*)d_in[1];
    const float* W   = (const float*)d_in[2];
    const float* a   = (const float*)d_in[3];
    float*       out = (float*)d_out;

    const int smemA = (4096 + 64 * 36) * 4;   // 25.2 KB
    cudaFuncSetAttribute(gat_wh,   cudaFuncAttributeMaxDynamicSharedMemorySize, smemA);
    cudaFuncSetAttribute(gat_attn, cudaFuncAttributeMaxDynamicSharedMemorySize, SM_TOTB);

    gat_wh<<<(B_ * N_) / 64, 256, smemA>>>(h, W, a);

    dim3 gridB(N_ / 128, B_);   // (16, 8) = 128 blocks
    gat_attn<<<gridB, 256, SM_TOTB>>>(adj, out);
}

// round 6
// speedup vs baseline: 5.4527x; 1.0845x over previous
#include <cuda_runtime.h>
#include <cstdint>

#define B_     8
#define N_     2048
#define FIN    256
#define FOUT   64
#define LOG2E  1.4426950408889634f

// Scratch (device globals: allocation-free rule)
__device__ float g_WhB[B_ * N_ * FOUT];   // [b][j>>3][o][j&7], tf32-pre-rounded
__device__ float g_esrc[B_ * N_];         // pre-scaled by log2(e)
__device__ float g_edst[B_ * N_];         // pre-scaled by log2(e)

// ---------------------------------------------------------------------------
// helpers
// ---------------------------------------------------------------------------
__device__ __forceinline__ uint32_t smem_u32(const void* p) {
    uint32_t a;
    asm("{ .reg .u64 t; cvta.to.shared.u64 t, %1; cvt.u32.u64 %0, t; }" : "=r"(a) : "l"(p));
    return a;
}
__device__ __forceinline__ void cpa16(uint32_t dst, const void* src) {
    asm volatile("cp.async.cg.shared.global [%0], [%1], 16;" :: "r"(dst), "l"(src));
}
#define CP_COMMIT() asm volatile("cp.async.commit_group;" ::: "memory")
#define CP_WAIT1()  asm volatile("cp.async.wait_group 1;" ::: "memory")

__device__ __forceinline__ float ex2f(float x) {
    float r; asm("ex2.approx.f32 %0, %1;" : "=f"(r) : "f"(x)); return r;
}
__device__ __forceinline__ uint32_t tf32u(float x) {
    uint32_t r; asm("cvt.rn.tf32.f32 %0, %1;" : "=r"(r) : "f"(x)); return r;
}
// D += A*B, m16n8k8 tf32 (base PTX ISA)
#define MMA_TF32(d, a0, a1, a2, a3, b0, b1)                                   \
    asm volatile("mma.sync.aligned.m16n8k8.row.col.f32.tf32.tf32.f32 "        \
                 "{%0,%1,%2,%3}, {%4,%5,%6,%7}, {%8,%9}, {%0,%1,%2,%3};"      \
                 : "+f"((d)[0]), "+f"((d)[1]), "+f"((d)[2]), "+f"((d)[3])     \
                 : "r"(a0), "r"(a1), "r"(a2), "r"(a3), "r"(b0), "r"(b1))

// packed fp32x2 FMA (kernel A)
#define FMA2(d, a, b) asm("fma.rn.f32x2 %0, %1, %2, %0;" : "+l"(d) : "l"(a), "l"(b))
__device__ __forceinline__ float pair_sum(unsigned long long v) {
    float lo, hi;
    asm("mov.b64 {%0, %1}, %2;" : "=f"(lo), "=f"(hi) : "l"(v));
    return lo + hi;
}
__device__ __forceinline__ unsigned long long pack2(float lo, float hi) {
    unsigned long long r;
    asm("mov.b64 %0, {%1, %2};" : "=l"(r) : "f"(lo), "f"(hi));
    return r;
}

// ---------------------------------------------------------------------------
// Kernel A: Wh = h @ W (fp32 FFMA2). 512 blocks x 256 threads, 32 rows/block.
// W staged per 16KB quarter; h chunks double-buffered via cp.async.
// Stores g_WhB (tf32, fragment layout) + e_src/e_dst pre-scaled by log2(e).
// ---------------------------------------------------------------------------
__global__ __launch_bounds__(256) void gat_wh(const float* __restrict__ h,
                                              const float* __restrict__ W,
                                              const float* __restrict__ a) {
    extern __shared__ float sA[];
    unsigned long long* Wp = (unsigned long long*)sA;   // 2048 ull = 16KB
    float* hb = sA + 4096;                              // 2 x (32 rows x 36)
    uint32_t hbase = smem_u32(sA) + 16384;

    int t = threadIdx.x;
    int rg = t >> 4, op = t & 15;
    int row0 = blockIdx.x * 32;

    // h chunk issue: 32 rows x 32 k = 256 x 16B, one cp.async per thread
    int hr = t >> 3, hf = t & 7;
    const float* hsrc0 = h + (size_t)(row0 + hr) * FIN + hf * 4;

    cpa16(hbase + hr * 144 + hf * 16, hsrc0);            CP_COMMIT();
    cpa16(hbase + 4608 + hr * 144 + hf * 16, hsrc0 + 32); CP_COMMIT();

    unsigned long long acc[2][4];
#pragma unroll
    for (int q = 0; q < 2; q++)
#pragma unroll
        for (int s = 0; s < 4; s++) acc[q][s] = 0ull;

    for (int wq = 0; wq < 4; wq++) {
        __syncthreads();   // previous compute done reading Wp
        // stage W quarter wq: 32 k-pairs x 64 outputs
        for (int idx = t; idx < 2048; idx += 256) {
            int kpl = idx >> 6, o = idx & 63;
            int kp = wq * 32 + kpl;
            Wp[idx] = pack2(W[(2 * kp) * FOUT + o], W[(2 * kp + 1) * FOUT + o]);
        }
        for (int kcq = 0; kcq < 2; kcq++) {
            int c = wq * 2 + kcq;
            CP_WAIT1();
            __syncthreads();
            const float* hc = hb + (c & 1) * 1152;
#pragma unroll
            for (int kpl = 0; kpl < 16; kpl++) {
                const ulonglong2* wrow = (const ulonglong2*)(Wp + (kcq * 16 + kpl) * 64);
                ulonglong2 wa = wrow[op];
                ulonglong2 wb = wrow[op + 16];
#pragma unroll
                for (int q = 0; q < 2; q++) {
                    unsigned long long hv =
                        *(const unsigned long long*)(hc + (rg * 2 + q) * 36 + 2 * kpl);
                    FMA2(acc[q][0], hv, wa.x);
                    FMA2(acc[q][1], hv, wa.y);
                    FMA2(acc[q][2], hv, wb.x);
                    FMA2(acc[q][3], hv, wb.y);
                }
            }
            __syncthreads();   // all done reading hb[c&1]
            if (c + 2 < 8)
                cpa16(hbase + (c & 1) * 4608 + hr * 144 + hf * 16, hsrc0 + (c + 2) * 32);
            CP_COMMIT();
        }
    }

    int ov[4] = {2 * op, 2 * op + 1, 2 * op + 32, 2 * op + 33};
    float a1v[4], a2v[4];
#pragma unroll
    for (int s = 0; s < 4; s++) { a1v[s] = a[ov[s]]; a2v[s] = a[FOUT + ov[s]]; }

#pragma unroll
    for (int q = 0; q < 2; q++) {
        int grow = row0 + rg * 2 + q;
        int b = grow >> 11, n = grow & (N_ - 1);
        float vals[4], v1 = 0.f, v2 = 0.f;
#pragma unroll
        for (int s = 0; s < 4; s++) {
            vals[s] = pair_sum(acc[q][s]);
            v1 += vals[s] * a1v[s];
            v2 += vals[s] * a2v[s];
        }
        size_t base = ((size_t)b * 256 + (n >> 3)) * 512 + (n & 7);
#pragma unroll
        for (int s = 0; s < 4; s++)
            g_WhB[base + (size_t)ov[s] * 8] = __uint_as_float(tf32u(vals[s]));
#pragma unroll
        for (int off = 1; off < 16; off <<= 1) {
            v1 += __shfl_xor_sync(0xffffffffu, v1, off);
            v2 += __shfl_xor_sync(0xffffffffu, v2, off);
        }
        if (op == 0) {
            g_esrc[grow] = v1 * LOG2E;
            g_edst[grow] = v2 * LOG2E;
        }
    }
}

// ---------------------------------------------------------------------------
// Kernel B: fused mask+leaky+exp2 -> mma.sync tf32 P @ Wh.
// Grid (32,8)=256 blocks x 256 threads (8 warps), 2 blocks/SM.
// Warp w: rh = w&1 (rows rh*32..+31), jq = w>>1 (j-quarter, 512 j).
// 16 chunks of 32 j per quarter (128 j staged per chunk, double-buffered).
// Epilogue: jq 1..3 dump partials to smem; jq 0 combines, normalizes, ELU.
// ---------------------------------------------------------------------------
#define SM_BUFSZ 33280             // 32KB B tiles (4 quarters x 8KB) + 512B edst
#define SM_TOTB  (2 * SM_BUFSZ)    // 66560

__device__ __forceinline__ void prefetch_chunk(uint32_t smdst, const char* whsrc,
                                               const float* edsrc, int cc, int t) {
#pragma unroll
    for (int it = 0; it < 8; it++) {
        int idx = it * 256 + t;          // 2048 x 16B
        int qd = idx >> 9, u = idx & 511;
        const char* src = whsrc + (size_t)(qd * 64 + cc * 4) * 2048 + (size_t)u * 16;
        cpa16(smdst + qd * 8192 + u * 16, src);
    }
    if (t < 32) {
        int qd = t >> 3, u = t & 7;
        const char* src = (const char*)(edsrc + qd * 512 + cc * 32 + u * 4);
        cpa16(smdst + 32768 + qd * 128 + u * 16, src);
    }
}

__global__ __launch_bounds__(256, 2) void gat_attn(const int* __restrict__ adj,
                                                   float* __restrict__ out) {
    extern __shared__ char sm[];
    uint32_t smb = smem_u32(sm);

    int t = threadIdx.x;
    int w = t >> 5, lane = t & 31;
    int q = lane >> 2, c = lane & 3;
    int b = blockIdx.y;
    int i0 = blockIdx.x * 64;
    int rowbase = b * N_;
    int rh = w & 1, jq = w >> 1;
    int wr = rh * 32;

    const char*  whsrc = (const char*)(g_WhB + (size_t)b * N_ * FOUT);
    const float* edsrc = g_edst + rowbase;

    float es[4];
#pragma unroll
    for (int r = 0; r < 4; r++) es[r] = g_esrc[rowbase + i0 + wr + q + 8 * r];

    const int* adjb = adj + (size_t)(rowbase + i0 + wr + q) * N_ + jq * 512;

    prefetch_chunk(smb, whsrc, edsrc, 0, t); CP_COMMIT();
    prefetch_chunk(smb + SM_BUFSZ, whsrc, edsrc, 1, t); CP_COMMIT();

    float acc[2][8][4];
#pragma unroll
    for (int f = 0; f < 2; f++)
#pragma unroll
        for (int nt = 0; nt < 8; nt++)
#pragma unroll
            for (int s = 0; s < 4; s++) acc[f][nt][s] = 0.f;
    float rsum[4] = {0.f, 0.f, 0.f, 0.f};

#pragma unroll 1
    for (int cc = 0; cc < 16; cc++) {
        CP_WAIT1();
        __syncthreads();
        const float* Bc = (const float*)(sm + (cc & 1) * SM_BUFSZ + jq * 8192);
        const float* Ec = (const float*)(sm + (cc & 1) * SM_BUFSZ + 32768 + jq * 128);

#pragma unroll
        for (int ks = 0; ks < 4; ks++) {
            float2 dv = *(const float2*)(Ec + ks * 8 + 2 * c);
            uint32_t pa[4][2];
#pragma unroll
            for (int r = 0; r < 4; r++) {
                int2 av = __ldcs((const int2*)(adjb + (size_t)(8 * r) * N_ +
                                               cc * 32 + ks * 8 + 2 * c));
                float x0 = es[r] + dv.x; x0 = fmaxf(x0, 0.2f * x0);
                float x1 = es[r] + dv.y; x1 = fmaxf(x1, 0.2f * x1);
                uint32_t u0 = tf32u(av.x > 0 ? ex2f(x0) : 0.f);
                uint32_t u1 = tf32u(av.y > 0 ? ex2f(x1) : 0.f);
                rsum[r] += __uint_as_float(u0) + __uint_as_float(u1);
                pa[r][0] = u0; pa[r][1] = u1;
            }
#pragma unroll
            for (int nt = 0; nt < 8; nt++) {
                float2 wv = *(const float2*)(Bc + ks * 512 + (nt * 8 + q) * 8 + 2 * c);
                uint32_t b0 = __float_as_uint(wv.x), b1 = __float_as_uint(wv.y);
                MMA_TF32(acc[0][nt], pa[0][0], pa[1][0], pa[0][1], pa[1][1], b0, b1);
                MMA_TF32(acc[1][nt], pa[2][0], pa[3][0], pa[2][1], pa[3][1], b0, b1);
            }
        }
        __syncthreads();
        if (cc + 2 < 16) prefetch_chunk(smb + (cc & 1) * SM_BUFSZ, whsrc, edsrc, cc + 2, t);
        CP_COMMIT();
    }

    // rowsum: reduce over the 4 c-lanes of each quad
#pragma unroll
    for (int r = 0; r < 4; r++) {
        rsum[r] += __shfl_xor_sync(0xffffffffu, rsum[r], 1);
        rsum[r] += __shfl_xor_sync(0xffffffffu, rsum[r], 2);
    }

    // combine the 4 j-quarters via smem (reuses staging buffers)
    float* dsm = (float*)sm;                 // [3][64][66]
    float* rsm = (float*)(sm + 50688);       // [3][64]
    __syncthreads();
    if (jq != 0) {
        float* dst = dsm + (jq - 1) * 4224;
#pragma unroll
        for (int f = 0; f < 2; f++) {
            int row0 = wr + 16 * f + q;
#pragma unroll
            for (int nt = 0; nt < 8; nt++) {
                *(float2*)(dst + row0 * 66 + nt * 8 + 2 * c) =
                    make_float2(acc[f][nt][0], acc[f][nt][1]);
                *(float2*)(dst + (row0 + 8) * 66 + nt * 8 + 2 * c) =
                    make_float2(acc[f][nt][2], acc[f][nt][3]);
            }
        }
        if (c == 0) {
#pragma unroll
            for (int r = 0; r < 4; r++)
                rsm[(jq - 1) * 64 + wr + q + 8 * r] = rsum[r];
        }
    }
    __syncthreads();
    if (jq == 0) {
        float inv_[4];
#pragma unroll
        for (int r = 0; r < 4; r++) {
            int row = wr + q + 8 * r;
            inv_[r] = 1.0f / (rsum[r] + rsm[row] + rsm[64 + row] + rsm[128 + row]);
        }
#pragma unroll
        for (int f = 0; f < 2; f++) {
            int row0 = wr + 16 * f + q;
            float i0v = inv_[2 * f], i1v = inv_[2 * f + 1];
            float* o0 = out + (size_t)(rowbase + i0 + row0) * FOUT;
            float* o1 = out + (size_t)(rowbase + i0 + row0 + 8) * FOUT;
#pragma unroll
            for (int nt = 0; nt < 8; nt++) {
                int col = nt * 8 + 2 * c;
                float s0x = acc[f][nt][0], s0y = acc[f][nt][1];
                float s1x = acc[f][nt][2], s1y = acc[f][nt][3];
#pragma unroll
                for (int p = 0; p < 3; p++) {
                    const float* dp = dsm + p * 4224;
                    float2 d0 = *(const float2*)(dp + row0 * 66 + col);
                    float2 d1 = *(const float2*)(dp + (row0 + 8) * 66 + col);
                    s0x += d0.x; s0y += d0.y;
                    s1x += d1.x; s1y += d1.y;
                }
                float y;
                float2 v0, v1;
                y = s0x * i0v; v0.x = y > 0.f ? y : expm1f(y);
                y = s0y * i0v; v0.y = y > 0.f ? y : expm1f(y);
                y = s1x * i1v; v1.x = y > 0.f ? y : expm1f(y);
                y = s1y * i1v; v1.y = y > 0.f ? y : expm1f(y);
                *(float2*)(o0 + col) = v0;
                *(float2*)(o1 + col) = v1;
            }
        }
    }
}

// ---------------------------------------------------------------------------
extern "C" void kernel_launch(void* const* d_in, const int* in_sizes, int n_in,
                              void* d_out, int out_size) {
    const float* h   = (const float*)d_in[0];
    const int*   adj = (const int*)d_in[1];
    const float* W   = (const float*)d_in[2];
    const float* a   = (const float*)d_in[3];
    float*       out = (float*)d_out;

    const int smemA = (4096 + 2 * 1152) * 4;   // 25.6 KB
    cudaFuncSetAttribute(gat_wh,   cudaFuncAttributeMaxDynamicSharedMemorySize, smemA);
    cudaFuncSetAttribute(gat_attn, cudaFuncAttributeMaxDynamicSharedMemorySize, SM_TOTB);

    gat_wh<<<(B_ * N_) / 32, 256, smemA>>>(h, W, a);

    dim3 gridB(N_ / 64, B_);   // (32, 8) = 256 blocks
    gat_attn<<<gridB, 256, SM_TOTB>>>(adj, out);
}